// round 7
// baseline (speedup 1.0000x reference)
#include <cuda_runtime.h>
#include <math.h>

#define NS 716
#define DD 64
#define NSAMP 48
#define NTILE 45            // ceil(716/16)
#define FINF 3.402823466e38f

// ---- scratch (device globals; no allocation) ----
__device__ float g_emb[NS * DD];
__device__ float g_Wh[NSAMP * NS * DD];
__device__ float g_Wh1[NSAMP * NS];
__device__ float g_Wh2[NSAMP * NS];
__device__ float g_q[NSAMP * NS * DD];
__device__ float g_kt2[NSAMP * 4 * 8 * 720 * 2];  // [s][h][c2][j] float2 pairs
__device__ float g_vt2[NSAMP * 4 * 8 * 720 * 2];  // [s][h][c2][j] float2 pairs
__device__ float g_cat[NSAMP * NS * 2 * DD];
__device__ unsigned g_cmask[NTILE * NS];
__device__ float g_wa1[DD];
__device__ float g_wa2[DD];
__device__ float g_Wc[DD * DD];   // Wo @ Wp[64:,:]
__device__ float g_bc[DD];        // bo @ Wp[64:,:] + bp

// ---- packed f32x2 helpers (sm_103a) ----
__device__ __forceinline__ unsigned long long pack2(float lo, float hi) {
    unsigned long long r;
    asm("mov.b64 %0, {%1, %2};" : "=l"(r) : "f"(lo), "f"(hi));
    return r;
}
__device__ __forceinline__ void unpack2(unsigned long long v, float& lo, float& hi) {
    asm("mov.b64 {%0, %1}, %2;" : "=f"(lo), "=f"(hi) : "l"(v));
}
__device__ __forceinline__ unsigned long long ffma2(unsigned long long a,
                                                    unsigned long long b,
                                                    unsigned long long c) {
    unsigned long long d;
    asm("fma.rn.f32x2 %0, %1, %2, %3;" : "=l"(d) : "l"(a), "l"(b), "l"(c));
    return d;
}

// ============================================================
// Kernel PRE: adjacency pack + embedding gather + weight prep
// ============================================================
__global__ void pre_kernel(const int* __restrict__ adj,
                           const float* __restrict__ in_emb,
                           const float* __restrict__ out_emb,
                           const int* __restrict__ ind,
                           const int* __restrict__ outd,
                           const float* __restrict__ W,
                           const float* __restrict__ a1, const float* __restrict__ a2,
                           const float* __restrict__ Wo, const float* __restrict__ bo,
                           const float* __restrict__ Wp, const float* __restrict__ bp) {
    int b = blockIdx.x, tid = threadIdx.x;
    if (b < 135) {
        int t = b / 3;
        int j = (b % 3) * 256 + tid;
        if (j < NS) {
            unsigned w = 0;
            #pragma unroll
            for (int ti = 0; ti < 16; ti++) {
                int i = t * 16 + ti;
                if (i < NS && adj[i * NS + j] != 0) w |= (1u << ti);
            }
            g_cmask[t * NS + j] = w;
        }
    } else if (b < 180) {
        int idx = (b - 135) * 256 + tid;
        if (idx < NS * 16) {
            int n = idx >> 4;
            int c4 = (idx & 15) * 4;
            float4 a = *(const float4*)&in_emb[ind[n] * DD + c4];
            float4 bb = *(const float4*)&out_emb[outd[n] * DD + c4];
            float4 r = {a.x + bb.x, a.y + bb.y, a.z + bb.z, a.w + bb.w};
            *(float4*)&g_emb[n * DD + c4] = r;
        }
    } else {
        if (tid < DD) {
            float s1 = 0.f, s2 = 0.f;
            #pragma unroll 8
            for (int c = 0; c < DD; c++) {
                float w = W[tid * DD + c];
                s1 = fmaf(w, a1[c], s1);
                s2 = fmaf(w, a2[c], s2);
            }
            g_wa1[tid] = s1; g_wa2[tid] = s2;
            float bsum = bp[tid];
            #pragma unroll 8
            for (int m = 0; m < DD; m++) bsum = fmaf(bo[m], Wp[(DD + m) * DD + tid], bsum);
            g_bc[tid] = bsum;
        }
        for (int o = tid; o < DD * DD; o += 256) {
            int k = o >> 6, c = o & 63;
            float acc = 0.f;
            #pragma unroll 8
            for (int m = 0; m < DD; m++)
                acc = fmaf(Wo[k * DD + m], Wp[(DD + m) * DD + c], acc);
            g_Wc[o] = acc;
        }
    }
}

// ============================================================
// Kernel B: fused projections (Wh, q, kt2, vt2) + Wh1/Wh2.
// grid (48, 23), block 256, 32 rows/block.
// ============================================================
#define BROWS 32
__global__ __launch_bounds__(256) void proj_kernel(
    const float* __restrict__ x,
    const float* __restrict__ W,  const float* __restrict__ Wq, const float* __restrict__ bq,
    const float* __restrict__ Wk, const float* __restrict__ bk,
    const float* __restrict__ Wv, const float* __restrict__ bv) {
    __shared__ float xs[BROWS][DD];
    __shared__ float ys[BROWS][DD];
    int s = blockIdx.x;
    int n0 = blockIdx.y * BROWS;
    int tid = threadIdx.x, lane = tid & 31, w = tid >> 5;

    #pragma unroll
    for (int half = 0; half < 2; half++) {
        int idx = half * 256 + tid;
        int r = idx >> 4, k4 = (idx & 15) * 4;
        int nn = min(n0 + r, NS - 1);
        float4 xv = *(const float4*)&x[(size_t)(s * NS + nn) * DD + k4];
        float4 ev = *(const float4*)&g_emb[nn * DD + k4];
        *(float4*)&xs[r][k4] = xv;
        float4 yv = {xv.x + ev.x, xv.y + ev.y, xv.z + ev.z, xv.w + ev.w};
        *(float4*)&ys[r][k4] = yv;
    }
    __syncthreads();

    // Wh1/Wh2
    {
        float wa10 = g_wa1[lane], wa11 = g_wa1[32 + lane];
        float wa20 = g_wa2[lane], wa21 = g_wa2[32 + lane];
        #pragma unroll
        for (int rr = 0; rr < 4; rr++) {
            int r = w * 4 + rr, n = n0 + r;
            float x0 = xs[r][lane], x1 = xs[r][32 + lane];
            float s1 = x0 * wa10 + x1 * wa11;
            float s2 = x0 * wa20 + x1 * wa21;
            #pragma unroll
            for (int off = 16; off; off >>= 1) {
                s1 += __shfl_xor_sync(0xffffffffu, s1, off);
                s2 += __shfl_xor_sync(0xffffffffu, s2, off);
            }
            if (lane == 0 && n < NS) {
                g_Wh1[s * NS + n] = s1;
                g_Wh2[s * NS + n] = s2;
            }
        }
    }

    int m = tid >> 6, c = tid & 63;
    const float* wp = (m == 0) ? W : (m == 1) ? Wq : (m == 2) ? Wk : Wv;
    float bias = 0.f;
    if (m == 1) bias = bq[c]; else if (m == 2) bias = bk[c]; else if (m == 3) bias = bv[c];

    float wcol[DD];
    #pragma unroll
    for (int k = 0; k < DD; k++) wcol[k] = wp[k * DD + c];

    int h = c >> 4, c2 = (c >> 1) & 7, phalf = c & 1;
    float* tp = ((m == 2) ? g_kt2 : g_vt2) +
                (size_t)(((s * 4 + h) * 8 + c2) * 720) * 2 + phalf;

    for (int r = 0; r < BROWS; r++) {
        int n = n0 + r;
        if (n >= NS) break;
        const float* src = (m == 0) ? xs[r] : ys[r];
        float acc = bias;
        #pragma unroll
        for (int k4 = 0; k4 < DD; k4 += 4) {
            float4 sv = *(const float4*)&src[k4];
            acc = fmaf(sv.x, wcol[k4],
                  fmaf(sv.y, wcol[k4 + 1],
                  fmaf(sv.z, wcol[k4 + 2],
                  fmaf(sv.w, wcol[k4 + 3], acc))));
        }
        if (m == 0)      g_Wh[(size_t)(s * NS + n) * DD + c] = acc;
        else if (m == 1) g_q[(size_t)(s * NS + n) * DD + c] = acc;
        else             tp[n * 2] = acc;
    }
}

// ============================================================
// Kernel D: GAT. grid (48,45), block 256.
// ============================================================
__global__ __launch_bounds__(256) void gat_kernel() {
    __shared__ float p[16][720];
    __shared__ float red[8][16];
    __shared__ float red1[8];
    __shared__ float smax;
    __shared__ float rowsum[16];

    int s = blockIdx.x, t = blockIdx.y;
    int i0 = t * 16;
    int tid = threadIdx.x, lane = tid & 31, w = tid >> 5;
    const unsigned* __restrict__ cm = g_cmask + t * NS;
    const float* __restrict__ wh2 = g_Wh2 + s * NS;

    float wh1[16];
    #pragma unroll
    for (int ti = 0; ti < 16; ti++) {
        int i = min(i0 + ti, NS - 1);
        wh1[ti] = g_Wh1[s * NS + i];
    }

    float lm = -FINF;
    for (int j = tid; j < NS; j += 256) lm = fmaxf(lm, wh2[j]);
    #pragma unroll
    for (int off = 16; off; off >>= 1)
        lm = fmaxf(lm, __shfl_xor_sync(0xffffffffu, lm, off));
    if (lane == 0) red1[w] = lm;
    __syncthreads();
    if (tid == 0) {
        float mm = red1[0];
        #pragma unroll
        for (int ww = 1; ww < 8; ww++) mm = fmaxf(mm, red1[ww]);
        smax = mm;
    }
    __syncthreads();

    float rme[16];
    {
        float mw = smax;
        #pragma unroll
        for (int ti = 0; ti < 16; ti++) {
            float e = wh1[ti] + mw;
            rme[ti] = fmaxf(e, 0.2f * e);
        }
    }

    float lsum[16];
    #pragma unroll
    for (int ti = 0; ti < 16; ti++) lsum[ti] = 0.f;
    for (int j = tid; j < NS; j += 256) {
        float w2 = wh2[j];
        unsigned mk = cm[j];
        #pragma unroll
        for (int ti = 0; ti < 16; ti++) {
            float e = wh1[ti] + w2;
            e = fmaxf(e, 0.2f * e);
            float pe = ((mk >> ti) & 1u) ? __expf(e - rme[ti]) : 0.0f;
            p[ti][j] = pe;
            lsum[ti] += pe;
        }
    }
    #pragma unroll
    for (int ti = 0; ti < 16; ti++)
        #pragma unroll
        for (int off = 16; off; off >>= 1)
            lsum[ti] += __shfl_xor_sync(0xffffffffu, lsum[ti], off);
    if (lane == 0) {
        #pragma unroll
        for (int ti = 0; ti < 16; ti++) red[w][ti] = lsum[ti];
    }
    __syncthreads();
    if (tid < 16) {
        float ss = red[0][tid];
        #pragma unroll
        for (int ww = 1; ww < 8; ww++) ss += red[ww][tid];
        rowsum[tid] = ss;
    }
    __syncthreads();

    int c = tid & 63, g = tid >> 6;
    float acc[16];
    #pragma unroll
    for (int ti = 0; ti < 16; ti++) acc[ti] = 0.f;
    const float* __restrict__ WhS = g_Wh + (size_t)s * NS * DD;
    for (int j0 = g * 4; j0 < NS; j0 += 16) {
        float wv0 = WhS[(size_t)(j0 + 0) * DD + c];
        float wv1 = WhS[(size_t)(j0 + 1) * DD + c];
        float wv2 = WhS[(size_t)(j0 + 2) * DD + c];
        float wv3 = WhS[(size_t)(j0 + 3) * DD + c];
        #pragma unroll
        for (int ti = 0; ti < 16; ti++) {
            float4 pv = *(const float4*)&p[ti][j0];
            acc[ti] = fmaf(pv.x, wv0, fmaf(pv.y, wv1,
                      fmaf(pv.z, wv2, fmaf(pv.w, wv3, acc[ti]))));
        }
    }
    __syncthreads();

    float* partial = &p[0][0];
    #pragma unroll
    for (int ti = 0; ti < 16; ti++) partial[(g * 16 + ti) * 64 + c] = acc[ti];
    __syncthreads();

    if (g == 0) {
        #pragma unroll
        for (int ti = 0; ti < 16; ti++) {
            int i = i0 + ti;
            if (i >= NS) continue;
            float v = (partial[ti * 64 + c] + partial[(16 + ti) * 64 + c] +
                       partial[(32 + ti) * 64 + c] + partial[(48 + ti) * 64 + c]) / rowsum[ti];
            v = v > 0.f ? v : expm1f(v);
            g_cat[(size_t)(s * NS + i) * 2 * DD + c] = v;
        }
    }
}

// ============================================================
// Kernel E: MHA single-pass, f32x2, no-max softmax.
// grid (48, 45, 4), block 256 (8 warps). Warp w owns queries i0+2w, i0+2w+1.
// ~100 regs -> 2 CTAs/SM, 16 warps resident.
// ============================================================
__global__ __launch_bounds__(256) void mha_kernel() {
    __shared__ unsigned long long red[8][16][33];   // 33.8 KB

    int s = blockIdx.x;
    int i0 = blockIdx.y * 16;
    int h = blockIdx.z;
    int tid = threadIdx.x, lane = tid & 31, w = tid >> 5;

    // q in registers, pre-scaled by 1/sqrt(16), packed as f32x2 pairs
    unsigned long long qreg[2][8];
    #pragma unroll
    for (int tq = 0; tq < 2; tq++) {
        int iq = min(i0 + w * 2 + tq, NS - 1);
        const float2* qp2 = (const float2*)(g_q + (size_t)(s * NS + iq) * DD + h * 16);
        #pragma unroll
        for (int c2 = 0; c2 < 8; c2++) {
            float2 v = qp2[c2];
            qreg[tq][c2] = pack2(v.x * 0.25f, v.y * 0.25f);
        }
    }

    const unsigned long long* __restrict__ kt =
        (const unsigned long long*)g_kt2 + (size_t)(s * 4 + h) * 8 * 720;
    const unsigned long long* __restrict__ vt =
        (const unsigned long long*)g_vt2 + (size_t)(s * 4 + h) * 8 * 720;

    unsigned long long acc2[2][8];
    #pragma unroll
    for (int tq = 0; tq < 2; tq++)
        #pragma unroll
        for (int c2 = 0; c2 < 8; c2++) acc2[tq][c2] = 0ull;
    float l[2] = {0.f, 0.f};

    for (int jb = 0; jb < NS; jb += 32) {
        int j = jb + lane;
        bool ok = j < NS;
        int jj = ok ? j : NS - 1;

        // QK (packed)
        unsigned long long sco2[2] = {0ull, 0ull};
        #pragma unroll
        for (int c2 = 0; c2 < 8; c2++) {
            unsigned long long kv = kt[c2 * 720 + jj];
            sco2[0] = ffma2(qreg[0][c2], kv, sco2[0]);
            sco2[1] = ffma2(qreg[1][c2], kv, sco2[1]);
        }
        // softmax numerator (no max subtraction: |score| <~ 12, fp32-safe)
        unsigned long long p2[2];
        #pragma unroll
        for (int tq = 0; tq < 2; tq++) {
            float lo, hi;
            unpack2(sco2[tq], lo, hi);
            float pe = ok ? __expf(lo + hi) : 0.0f;
            l[tq] += pe;
            p2[tq] = pack2(pe, pe);
        }
        // PV (packed)
        #pragma unroll
        for (int c2 = 0; c2 < 8; c2++) {
            unsigned long long vv = vt[c2 * 720 + jj];
            acc2[0][c2] = ffma2(p2[0], vv, acc2[0][c2]);
            acc2[1][c2] = ffma2(p2[1], vv, acc2[1][c2]);
        }
    }

    // reduce l across lanes
    #pragma unroll
    for (int tq = 0; tq < 2; tq++)
        #pragma unroll
        for (int off = 16; off; off >>= 1)
            l[tq] += __shfl_xor_sync(0xffffffffu, l[tq], off);
    float linv[2] = {1.0f / l[0], 1.0f / l[1]};

    // reduce acc2 across lanes via smem transpose, single pass (2q x 8c2 = 16 rows)
    #pragma unroll
    for (int tq = 0; tq < 2; tq++)
        #pragma unroll
        for (int c2 = 0; c2 < 8; c2++)
            red[w][tq * 8 + c2][lane] = acc2[tq][c2];
    __syncwarp();
    {
        int tql = lane >> 4, cl = lane & 15;
        const float* base = (const float*)&red[w][tql * 8 + (cl >> 1)][0];
        int hf = cl & 1;
        float v = 0.f;
        #pragma unroll
        for (int ll = 0; ll < 32; ll++) v += base[ll * 2 + hf];
        int i = i0 + w * 2 + tql;
        if (i < NS)
            g_cat[(size_t)(s * NS + i) * 2 * DD + DD + h * 16 + cl] = v * linv[tql];
    }
}

// ============================================================
// Kernel F: final projection, 16 rows/block, 4-way k-split.
// ============================================================
__global__ __launch_bounds__(256) void final_kernel(const float* __restrict__ Wp,
                                                    float* __restrict__ out) {
    __shared__ float cs[16][2 * DD];
    __shared__ float pa[4][16][64];
    int s = blockIdx.x;
    int n0 = blockIdx.y * 16;
    int tid = threadIdx.x;

    #pragma unroll
    for (int half = 0; half < 2; half++) {
        int idx = half * 256 + tid;
        int r = idx >> 5, k4 = (idx & 31) * 4;
        int nn = min(n0 + r, NS - 1);
        *(float4*)&cs[r][k4] = *(const float4*)&g_cat[(size_t)(s * NS + nn) * 2 * DD + k4];
    }
    __syncthreads();

    int c = tid & 63, kg = tid >> 6;
    float acc[16];
    #pragma unroll
    for (int r = 0; r < 16; r++) acc[r] = 0.f;
    for (int k0 = kg * 32; k0 < kg * 32 + 32; k0 += 4) {
        const float* wsrc = (k0 < 64) ? (Wp + k0 * DD) : (g_Wc + (k0 - 64) * DD);
        float wv0 = wsrc[c];
        float wv1 = wsrc[DD + c];
        float wv2 = wsrc[2 * DD + c];
        float wv3 = wsrc[3 * DD + c];
        #pragma unroll
        for (int r = 0; r < 16; r++) {
            float4 cv = *(const float4*)&cs[r][k0];
            acc[r] = fmaf(cv.x, wv0, fmaf(cv.y, wv1,
                     fmaf(cv.z, wv2, fmaf(cv.w, wv3, acc[r]))));
        }
    }
    #pragma unroll
    for (int r = 0; r < 16; r++) pa[kg][r][c] = acc[r];
    __syncthreads();

    if (kg == 0) {
        #pragma unroll
        for (int r = 0; r < 16; r++) {
            int n = n0 + r;
            if (n < NS)
                out[(size_t)(s * NS + n) * DD + c] =
                    pa[0][r][c] + pa[1][r][c] + pa[2][r][c] + pa[3][r][c] + g_bc[c];
        }
    }
}

// ============================================================
extern "C" void kernel_launch(void* const* d_in, const int* in_sizes, int n_in,
                              void* d_out, int out_size) {
    const float* x      = (const float*)d_in[0];
    const int*   adj    = (const int*)d_in[1];
    const int*   ind    = (const int*)d_in[2];
    const int*   outd   = (const int*)d_in[3];
    const float* in_emb = (const float*)d_in[4];
    const float* out_emb= (const float*)d_in[5];
    const float* W      = (const float*)d_in[6];
    const float* a1     = (const float*)d_in[7];
    const float* a2     = (const float*)d_in[8];
    const float* Wq     = (const float*)d_in[9];
    const float* bq     = (const float*)d_in[10];
    const float* Wk     = (const float*)d_in[11];
    const float* bk     = (const float*)d_in[12];
    const float* Wv     = (const float*)d_in[13];
    const float* bv     = (const float*)d_in[14];
    const float* Wo     = (const float*)d_in[15];
    const float* bo     = (const float*)d_in[16];
    const float* Wp     = (const float*)d_in[17];
    const float* bp     = (const float*)d_in[18];
    float* out = (float*)d_out;

    pre_kernel<<<181, 256>>>(adj, in_emb, out_emb, ind, outd, W, a1, a2, Wo, bo, Wp, bp);
    proj_kernel<<<dim3(NSAMP, (NS + BROWS - 1) / BROWS), 256>>>(x, W, Wq, bq, Wk, bk, Wv, bv);
    gat_kernel<<<dim3(NSAMP, NTILE), 256>>>();
    mha_kernel<<<dim3(NSAMP, NTILE, 4), 256>>>();
    final_kernel<<<dim3(NSAMP, NTILE), 256>>>(Wp, out);
}

// round 8
// speedup vs baseline: 1.0539x; 1.0539x over previous
#include <cuda_runtime.h>
#include <math.h>

#define NS 716
#define DD 64
#define NSAMP 48
#define NTILE 45            // ceil(716/16)
#define FINF 3.402823466e38f

// ---- scratch (device globals; no allocation) ----
__device__ float g_emb[NS * DD];
__device__ float g_Wh[NSAMP * NS * DD];
__device__ float g_Wh1[NSAMP * NS];
__device__ float g_Wh2[NSAMP * NS];
__device__ float g_q[NSAMP * NS * DD];
__device__ float g_kt2[NSAMP * 4 * 8 * 720 * 2];  // [s][h][c2][j] float2 pairs
__device__ float g_vt2[NSAMP * 4 * 8 * 720 * 2];  // [s][h][c2][j] float2 pairs
__device__ float g_cat[NSAMP * NS * 2 * DD];
__device__ unsigned g_cmask[NTILE * NS];
__device__ float g_wa1[DD];
__device__ float g_wa2[DD];
__device__ float g_Wc[DD * DD];   // Wo @ Wp[64:,:]
__device__ float g_bc[DD];        // bo @ Wp[64:,:] + bp

// ---- packed f32x2 helpers (sm_103a) ----
__device__ __forceinline__ unsigned long long pack2(float lo, float hi) {
    unsigned long long r;
    asm("mov.b64 %0, {%1, %2};" : "=l"(r) : "f"(lo), "f"(hi));
    return r;
}
__device__ __forceinline__ void unpack2(unsigned long long v, float& lo, float& hi) {
    asm("mov.b64 {%0, %1}, %2;" : "=f"(lo), "=f"(hi) : "l"(v));
}
__device__ __forceinline__ unsigned long long ffma2(unsigned long long a,
                                                    unsigned long long b,
                                                    unsigned long long c) {
    unsigned long long d;
    asm("fma.rn.f32x2 %0, %1, %2, %3;" : "=l"(d) : "l"(a), "l"(b), "l"(c));
    return d;
}

// ============================================================
// Kernel PRE: adjacency pack + embedding gather + weight prep
// ============================================================
__global__ void pre_kernel(const int* __restrict__ adj,
                           const float* __restrict__ in_emb,
                           const float* __restrict__ out_emb,
                           const int* __restrict__ ind,
                           const int* __restrict__ outd,
                           const float* __restrict__ W,
                           const float* __restrict__ a1, const float* __restrict__ a2,
                           const float* __restrict__ Wo, const float* __restrict__ bo,
                           const float* __restrict__ Wp, const float* __restrict__ bp) {
    int b = blockIdx.x, tid = threadIdx.x;
    if (b < 135) {
        int t = b / 3;
        int j = (b % 3) * 256 + tid;
        if (j < NS) {
            unsigned w = 0;
            #pragma unroll
            for (int ti = 0; ti < 16; ti++) {
                int i = t * 16 + ti;
                if (i < NS && adj[i * NS + j] != 0) w |= (1u << ti);
            }
            g_cmask[t * NS + j] = w;
        }
    } else if (b < 180) {
        int idx = (b - 135) * 256 + tid;
        if (idx < NS * 16) {
            int n = idx >> 4;
            int c4 = (idx & 15) * 4;
            float4 a = *(const float4*)&in_emb[ind[n] * DD + c4];
            float4 bb = *(const float4*)&out_emb[outd[n] * DD + c4];
            float4 r = {a.x + bb.x, a.y + bb.y, a.z + bb.z, a.w + bb.w};
            *(float4*)&g_emb[n * DD + c4] = r;
        }
    } else {
        if (tid < DD) {
            float s1 = 0.f, s2 = 0.f;
            #pragma unroll 8
            for (int c = 0; c < DD; c++) {
                float w = W[tid * DD + c];
                s1 = fmaf(w, a1[c], s1);
                s2 = fmaf(w, a2[c], s2);
            }
            g_wa1[tid] = s1; g_wa2[tid] = s2;
            float bsum = bp[tid];
            #pragma unroll 8
            for (int m = 0; m < DD; m++) bsum = fmaf(bo[m], Wp[(DD + m) * DD + tid], bsum);
            g_bc[tid] = bsum;
        }
        for (int o = tid; o < DD * DD; o += 256) {
            int k = o >> 6, c = o & 63;
            float acc = 0.f;
            #pragma unroll 8
            for (int m = 0; m < DD; m++)
                acc = fmaf(Wo[k * DD + m], Wp[(DD + m) * DD + c], acc);
            g_Wc[o] = acc;
        }
    }
}

// ============================================================
// Kernel B: fused projections (Wh, q, kt2, vt2) + Wh1/Wh2.
// grid (48, 23), block 256, 32 rows/block.
// ============================================================
#define BROWS 32
__global__ __launch_bounds__(256) void proj_kernel(
    const float* __restrict__ x,
    const float* __restrict__ W,  const float* __restrict__ Wq, const float* __restrict__ bq,
    const float* __restrict__ Wk, const float* __restrict__ bk,
    const float* __restrict__ Wv, const float* __restrict__ bv) {
    __shared__ float xs[BROWS][DD];
    __shared__ float ys[BROWS][DD];
    int s = blockIdx.x;
    int n0 = blockIdx.y * BROWS;
    int tid = threadIdx.x, lane = tid & 31, w = tid >> 5;

    #pragma unroll
    for (int half = 0; half < 2; half++) {
        int idx = half * 256 + tid;
        int r = idx >> 4, k4 = (idx & 15) * 4;
        int nn = min(n0 + r, NS - 1);
        float4 xv = *(const float4*)&x[(size_t)(s * NS + nn) * DD + k4];
        float4 ev = *(const float4*)&g_emb[nn * DD + k4];
        *(float4*)&xs[r][k4] = xv;
        float4 yv = {xv.x + ev.x, xv.y + ev.y, xv.z + ev.z, xv.w + ev.w};
        *(float4*)&ys[r][k4] = yv;
    }
    __syncthreads();

    // Wh1/Wh2
    {
        float wa10 = g_wa1[lane], wa11 = g_wa1[32 + lane];
        float wa20 = g_wa2[lane], wa21 = g_wa2[32 + lane];
        #pragma unroll
        for (int rr = 0; rr < 4; rr++) {
            int r = w * 4 + rr, n = n0 + r;
            float x0 = xs[r][lane], x1 = xs[r][32 + lane];
            float s1 = x0 * wa10 + x1 * wa11;
            float s2 = x0 * wa20 + x1 * wa21;
            #pragma unroll
            for (int off = 16; off; off >>= 1) {
                s1 += __shfl_xor_sync(0xffffffffu, s1, off);
                s2 += __shfl_xor_sync(0xffffffffu, s2, off);
            }
            if (lane == 0 && n < NS) {
                g_Wh1[s * NS + n] = s1;
                g_Wh2[s * NS + n] = s2;
            }
        }
    }

    int m = tid >> 6, c = tid & 63;
    const float* wp = (m == 0) ? W : (m == 1) ? Wq : (m == 2) ? Wk : Wv;
    float bias = 0.f;
    if (m == 1) bias = bq[c]; else if (m == 2) bias = bk[c]; else if (m == 3) bias = bv[c];

    float wcol[DD];
    #pragma unroll
    for (int k = 0; k < DD; k++) wcol[k] = wp[k * DD + c];

    int h = c >> 4, c2 = (c >> 1) & 7, phalf = c & 1;
    float* tp = ((m == 2) ? g_kt2 : g_vt2) +
                (size_t)(((s * 4 + h) * 8 + c2) * 720) * 2 + phalf;

    for (int r = 0; r < BROWS; r++) {
        int n = n0 + r;
        if (n >= NS) break;
        const float* src = (m == 0) ? xs[r] : ys[r];
        float acc = bias;
        #pragma unroll
        for (int k4 = 0; k4 < DD; k4 += 4) {
            float4 sv = *(const float4*)&src[k4];
            acc = fmaf(sv.x, wcol[k4],
                  fmaf(sv.y, wcol[k4 + 1],
                  fmaf(sv.z, wcol[k4 + 2],
                  fmaf(sv.w, wcol[k4 + 3], acc))));
        }
        if (m == 0)      g_Wh[(size_t)(s * NS + n) * DD + c] = acc;
        else if (m == 1) g_q[(size_t)(s * NS + n) * DD + c] = acc;
        else             tp[n * 2] = acc;
    }
}

// ============================================================
// Kernel D: GAT. grid (48,45), block 256.
// ============================================================
__global__ __launch_bounds__(256) void gat_kernel() {
    __shared__ float p[16][720];
    __shared__ float red[8][16];
    __shared__ float red1[8];
    __shared__ float smax;
    __shared__ float rowsum[16];

    int s = blockIdx.x, t = blockIdx.y;
    int i0 = t * 16;
    int tid = threadIdx.x, lane = tid & 31, w = tid >> 5;
    const unsigned* __restrict__ cm = g_cmask + t * NS;
    const float* __restrict__ wh2 = g_Wh2 + s * NS;

    float wh1[16];
    #pragma unroll
    for (int ti = 0; ti < 16; ti++) {
        int i = min(i0 + ti, NS - 1);
        wh1[ti] = g_Wh1[s * NS + i];
    }

    float lm = -FINF;
    for (int j = tid; j < NS; j += 256) lm = fmaxf(lm, wh2[j]);
    #pragma unroll
    for (int off = 16; off; off >>= 1)
        lm = fmaxf(lm, __shfl_xor_sync(0xffffffffu, lm, off));
    if (lane == 0) red1[w] = lm;
    __syncthreads();
    if (tid == 0) {
        float mm = red1[0];
        #pragma unroll
        for (int ww = 1; ww < 8; ww++) mm = fmaxf(mm, red1[ww]);
        smax = mm;
    }
    __syncthreads();

    float rme[16];
    {
        float mw = smax;
        #pragma unroll
        for (int ti = 0; ti < 16; ti++) {
            float e = wh1[ti] + mw;
            rme[ti] = fmaxf(e, 0.2f * e);
        }
    }

    float lsum[16];
    #pragma unroll
    for (int ti = 0; ti < 16; ti++) lsum[ti] = 0.f;
    for (int j = tid; j < NS; j += 256) {
        float w2 = wh2[j];
        unsigned mk = cm[j];
        #pragma unroll
        for (int ti = 0; ti < 16; ti++) {
            float e = wh1[ti] + w2;
            e = fmaxf(e, 0.2f * e);
            float pe = ((mk >> ti) & 1u) ? __expf(e - rme[ti]) : 0.0f;
            p[ti][j] = pe;
            lsum[ti] += pe;
        }
    }
    #pragma unroll
    for (int ti = 0; ti < 16; ti++)
        #pragma unroll
        for (int off = 16; off; off >>= 1)
            lsum[ti] += __shfl_xor_sync(0xffffffffu, lsum[ti], off);
    if (lane == 0) {
        #pragma unroll
        for (int ti = 0; ti < 16; ti++) red[w][ti] = lsum[ti];
    }
    __syncthreads();
    if (tid < 16) {
        float ss = red[0][tid];
        #pragma unroll
        for (int ww = 1; ww < 8; ww++) ss += red[ww][tid];
        rowsum[tid] = ss;
    }
    __syncthreads();

    int c = tid & 63, g = tid >> 6;
    float acc[16];
    #pragma unroll
    for (int ti = 0; ti < 16; ti++) acc[ti] = 0.f;
    const float* __restrict__ WhS = g_Wh + (size_t)s * NS * DD;
    for (int j0 = g * 4; j0 < NS; j0 += 16) {
        float wv0 = WhS[(size_t)(j0 + 0) * DD + c];
        float wv1 = WhS[(size_t)(j0 + 1) * DD + c];
        float wv2 = WhS[(size_t)(j0 + 2) * DD + c];
        float wv3 = WhS[(size_t)(j0 + 3) * DD + c];
        #pragma unroll
        for (int ti = 0; ti < 16; ti++) {
            float4 pv = *(const float4*)&p[ti][j0];
            acc[ti] = fmaf(pv.x, wv0, fmaf(pv.y, wv1,
                      fmaf(pv.z, wv2, fmaf(pv.w, wv3, acc[ti]))));
        }
    }
    __syncthreads();

    float* partial = &p[0][0];
    #pragma unroll
    for (int ti = 0; ti < 16; ti++) partial[(g * 16 + ti) * 64 + c] = acc[ti];
    __syncthreads();

    if (g == 0) {
        #pragma unroll
        for (int ti = 0; ti < 16; ti++) {
            int i = i0 + ti;
            if (i >= NS) continue;
            float v = (partial[ti * 64 + c] + partial[(16 + ti) * 64 + c] +
                       partial[(32 + ti) * 64 + c] + partial[(48 + ti) * 64 + c]) / rowsum[ti];
            v = v > 0.f ? v : expm1f(v);
            g_cat[(size_t)(s * NS + i) * 2 * DD + c] = v;
        }
    }
}

// ============================================================
// Kernel E: MHA — smem-staged k/v tiles, 4 queries/warp, f32x2.
// grid (48, 45, 4), block 128 (4 warps). k/v loaded ONCE per block.
// ============================================================
__global__ __launch_bounds__(128, 3) void mha_kernel() {
    __shared__ unsigned long long sbuf[2176];  // k:[0,1024) v:[1024,2048); red overlay

    int s = blockIdx.x;
    int i0 = blockIdx.y * 16;
    int h = blockIdx.z;
    int tid = threadIdx.x, lane = tid & 31, w = tid >> 5;

    // q in registers, pre-scaled by 1/sqrt(16)
    unsigned long long qreg[4][8];
    #pragma unroll
    for (int tq = 0; tq < 4; tq++) {
        int iq = min(i0 + w * 4 + tq, NS - 1);
        const float2* qp2 = (const float2*)(g_q + (size_t)(s * NS + iq) * DD + h * 16);
        #pragma unroll
        for (int c2 = 0; c2 < 8; c2++) {
            float2 v = qp2[c2];
            qreg[tq][c2] = pack2(v.x * 0.25f, v.y * 0.25f);
        }
    }

    const float* __restrict__ ktf = g_kt2 + (size_t)(s * 4 + h) * 8 * 720 * 2;
    const float* __restrict__ vtf = g_vt2 + (size_t)(s * 4 + h) * 8 * 720 * 2;
    float* ksf = (float*)sbuf;
    float* vsf = (float*)(sbuf + 1024);
    const unsigned long long* ks = sbuf;
    const unsigned long long* vs = sbuf + 1024;

    unsigned long long acc2[4][8];
    #pragma unroll
    for (int tq = 0; tq < 4; tq++)
        #pragma unroll
        for (int c2 = 0; c2 < 8; c2++) acc2[tq][c2] = 0ull;
    float l[4] = {0.f, 0.f, 0.f, 0.f};

    for (int t = 0; t < 6; t++) {
        int jb = t * 128;
        __syncthreads();   // prior tile's reads done
        // cooperative fill: k tile 8x128 ull + v tile (float4 = 2 j-pairs per c2)
        #pragma unroll
        for (int i = 0; i < 4; i++) {
            int f = i * 128 + tid;            // 0..511
            int c2 = f >> 6, jp = f & 63;
            int j = jb + jp * 2;              // j even; j<NS => j+1<NS (NS even)
            float4 kv = {0.f, 0.f, 0.f, 0.f}, vv = {0.f, 0.f, 0.f, 0.f};
            if (j < NS) {
                kv = *(const float4*)&ktf[(c2 * 720 + j) * 2];
                vv = *(const float4*)&vtf[(c2 * 720 + j) * 2];
            }
            *(float4*)&ksf[(c2 * 128 + jp * 2) * 2] = kv;
            *(float4*)&vsf[(c2 * 128 + jp * 2) * 2] = vv;
        }
        __syncthreads();   // fill visible

        #pragma unroll
        for (int sub = 0; sub < 4; sub++) {
            int jl = sub * 32 + lane;
            bool ok = (jb + jl) < NS;
            // QK from smem
            unsigned long long sco2[4] = {0ull, 0ull, 0ull, 0ull};
            #pragma unroll
            for (int c2 = 0; c2 < 8; c2++) {
                unsigned long long kv = ks[c2 * 128 + jl];
                sco2[0] = ffma2(qreg[0][c2], kv, sco2[0]);
                sco2[1] = ffma2(qreg[1][c2], kv, sco2[1]);
                sco2[2] = ffma2(qreg[2][c2], kv, sco2[2]);
                sco2[3] = ffma2(qreg[3][c2], kv, sco2[3]);
            }
            // softmax numerator (no max: |score| small, fp32-safe)
            unsigned long long p2[4];
            #pragma unroll
            for (int tq = 0; tq < 4; tq++) {
                float lo, hi;
                unpack2(sco2[tq], lo, hi);
                float pe = ok ? __expf(lo + hi) : 0.0f;
                l[tq] += pe;
                p2[tq] = pack2(pe, pe);
            }
            // PV from smem
            #pragma unroll
            for (int c2 = 0; c2 < 8; c2++) {
                unsigned long long vv = vs[c2 * 128 + jl];
                acc2[0][c2] = ffma2(p2[0], vv, acc2[0][c2]);
                acc2[1][c2] = ffma2(p2[1], vv, acc2[1][c2]);
                acc2[2][c2] = ffma2(p2[2], vv, acc2[2][c2]);
                acc2[3][c2] = ffma2(p2[3], vv, acc2[3][c2]);
            }
        }
    }

    // reduce l across lanes
    #pragma unroll
    for (int tq = 0; tq < 4; tq++)
        #pragma unroll
        for (int off = 16; off; off >>= 1)
            l[tq] += __shfl_xor_sync(0xffffffffu, l[tq], off);
    float linv[4];
    #pragma unroll
    for (int tq = 0; tq < 4; tq++) linv[tq] = 1.0f / l[tq];

    __syncthreads();   // all smem tile reads done before overlay
    unsigned long long* red = sbuf + w * 528;   // [16][33] per warp
    #pragma unroll
    for (int ps = 0; ps < 2; ps++) {
        #pragma unroll
        for (int tq2 = 0; tq2 < 2; tq2++)
            #pragma unroll
            for (int c2 = 0; c2 < 8; c2++)
                red[(tq2 * 8 + c2) * 33 + lane] = acc2[ps * 2 + tq2][c2];
        __syncwarp();
        int tql = lane >> 4, cl = lane & 15;
        const float* base = (const float*)&red[(tql * 8 + (cl >> 1)) * 33];
        int hf = cl & 1;
        float v = 0.f;
        #pragma unroll
        for (int ll = 0; ll < 32; ll++) v += base[ll * 2 + hf];
        float li = linv[ps * 2 + tql];
        int i = i0 + w * 4 + ps * 2 + tql;
        if (i < NS)
            g_cat[(size_t)(s * NS + i) * 2 * DD + DD + h * 16 + cl] = v * li;
        __syncwarp();
    }
}

// ============================================================
// Kernel F: final projection, 16 rows/block, 4-way k-split.
// ============================================================
__global__ __launch_bounds__(256) void final_kernel(const float* __restrict__ Wp,
                                                    float* __restrict__ out) {
    __shared__ float cs[16][2 * DD];
    __shared__ float pa[4][16][64];
    int s = blockIdx.x;
    int n0 = blockIdx.y * 16;
    int tid = threadIdx.x;

    #pragma unroll
    for (int half = 0; half < 2; half++) {
        int idx = half * 256 + tid;
        int r = idx >> 5, k4 = (idx & 31) * 4;
        int nn = min(n0 + r, NS - 1);
        *(float4*)&cs[r][k4] = *(const float4*)&g_cat[(size_t)(s * NS + nn) * 2 * DD + k4];
    }
    __syncthreads();

    int c = tid & 63, kg = tid >> 6;
    float acc[16];
    #pragma unroll
    for (int r = 0; r < 16; r++) acc[r] = 0.f;
    for (int k0 = kg * 32; k0 < kg * 32 + 32; k0 += 4) {
        const float* wsrc = (k0 < 64) ? (Wp + k0 * DD) : (g_Wc + (k0 - 64) * DD);
        float wv0 = wsrc[c];
        float wv1 = wsrc[DD + c];
        float wv2 = wsrc[2 * DD + c];
        float wv3 = wsrc[3 * DD + c];
        #pragma unroll
        for (int r = 0; r < 16; r++) {
            float4 cv = *(const float4*)&cs[r][k0];
            acc[r] = fmaf(cv.x, wv0, fmaf(cv.y, wv1,
                     fmaf(cv.z, wv2, fmaf(cv.w, wv3, acc[r]))));
        }
    }
    #pragma unroll
    for (int r = 0; r < 16; r++) pa[kg][r][c] = acc[r];
    __syncthreads();

    if (kg == 0) {
        #pragma unroll
        for (int r = 0; r < 16; r++) {
            int n = n0 + r;
            if (n < NS)
                out[(size_t)(s * NS + n) * DD + c] =
                    pa[0][r][c] + pa[1][r][c] + pa[2][r][c] + pa[3][r][c] + g_bc[c];
        }
    }
}

// ============================================================
extern "C" void kernel_launch(void* const* d_in, const int* in_sizes, int n_in,
                              void* d_out, int out_size) {
    const float* x      = (const float*)d_in[0];
    const int*   adj    = (const int*)d_in[1];
    const int*   ind    = (const int*)d_in[2];
    const int*   outd   = (const int*)d_in[3];
    const float* in_emb = (const float*)d_in[4];
    const float* out_emb= (const float*)d_in[5];
    const float* W      = (const float*)d_in[6];
    const float* a1     = (const float*)d_in[7];
    const float* a2     = (const float*)d_in[8];
    const float* Wq     = (const float*)d_in[9];
    const float* bq     = (const float*)d_in[10];
    const float* Wk     = (const float*)d_in[11];
    const float* bk     = (const float*)d_in[12];
    const float* Wv     = (const float*)d_in[13];
    const float* bv     = (const float*)d_in[14];
    const float* Wo     = (const float*)d_in[15];
    const float* bo     = (const float*)d_in[16];
    const float* Wp     = (const float*)d_in[17];
    const float* bp     = (const float*)d_in[18];
    float* out = (float*)d_out;

    pre_kernel<<<181, 256>>>(adj, in_emb, out_emb, ind, outd, W, a1, a2, Wo, bo, Wp, bp);
    proj_kernel<<<dim3(NSAMP, (NS + BROWS - 1) / BROWS), 256>>>(x, W, Wq, bq, Wk, bk, Wv, bv);
    gat_kernel<<<dim3(NSAMP, NTILE), 256>>>();
    mha_kernel<<<dim3(NSAMP, NTILE, 4), 128>>>();
    final_kernel<<<dim3(NSAMP, NTILE), 256>>>(Wp, out);
}

// round 9
// speedup vs baseline: 1.1956x; 1.1345x over previous
#include <cuda_runtime.h>
#include <math.h>

#define NS 716
#define DD 64
#define NSAMP 48
#define NTILE 45            // ceil(716/16)
#define FINF 3.402823466e38f

// ---- scratch (device globals; no allocation) ----
__device__ float g_emb[NS * DD];
__device__ float g_Wh[NSAMP * NS * DD];
__device__ float g_Wh1[NSAMP * NS];
__device__ float g_Wh2[NSAMP * NS];
__device__ float g_q[NSAMP * NS * DD];
__device__ float g_kt2[NSAMP * 4 * 8 * 720 * 2];  // [s][h][c2][j] float2 pairs
__device__ float g_vt2[NSAMP * 4 * 8 * 720 * 2];  // [s][h][c2][j] float2 pairs
__device__ float g_cat[NSAMP * NS * 2 * DD];
__device__ unsigned g_cmask[NTILE * NS];
__device__ float g_wa1[DD];
__device__ float g_wa2[DD];
__device__ float g_Wc[DD * DD];   // Wo @ Wp[64:,:]
__device__ float g_bc[DD];        // bo @ Wp[64:,:] + bp

// ---- packed f32x2 helpers (sm_103a) ----
__device__ __forceinline__ unsigned long long pack2(float lo, float hi) {
    unsigned long long r;
    asm("mov.b64 %0, {%1, %2};" : "=l"(r) : "f"(lo), "f"(hi));
    return r;
}
__device__ __forceinline__ void unpack2(unsigned long long v, float& lo, float& hi) {
    asm("mov.b64 {%0, %1}, %2;" : "=f"(lo), "=f"(hi) : "l"(v));
}
__device__ __forceinline__ unsigned long long ffma2(unsigned long long a,
                                                    unsigned long long b,
                                                    unsigned long long c) {
    unsigned long long d;
    asm("fma.rn.f32x2 %0, %1, %2, %3;" : "=l"(d) : "l"(a), "l"(b), "l"(c));
    return d;
}
__device__ __forceinline__ void cp_async16(unsigned sa, const void* g) {
    asm volatile("cp.async.cg.shared.global [%0], [%1], 16;" :: "r"(sa), "l"(g));
}

// ============================================================
// Kernel PRE: adjacency pack + embedding gather + weight prep
// ============================================================
__global__ void pre_kernel(const int* __restrict__ adj,
                           const float* __restrict__ in_emb,
                           const float* __restrict__ out_emb,
                           const int* __restrict__ ind,
                           const int* __restrict__ outd,
                           const float* __restrict__ W,
                           const float* __restrict__ a1, const float* __restrict__ a2,
                           const float* __restrict__ Wo, const float* __restrict__ bo,
                           const float* __restrict__ Wp, const float* __restrict__ bp) {
    int b = blockIdx.x, tid = threadIdx.x;
    if (b < 135) {
        int t = b / 3;
        int j = (b % 3) * 256 + tid;
        if (j < NS) {
            unsigned w = 0;
            #pragma unroll
            for (int ti = 0; ti < 16; ti++) {
                int i = t * 16 + ti;
                if (i < NS && adj[i * NS + j] != 0) w |= (1u << ti);
            }
            g_cmask[t * NS + j] = w;
        }
    } else if (b < 180) {
        int idx = (b - 135) * 256 + tid;
        if (idx < NS * 16) {
            int n = idx >> 4;
            int c4 = (idx & 15) * 4;
            float4 a = *(const float4*)&in_emb[ind[n] * DD + c4];
            float4 bb = *(const float4*)&out_emb[outd[n] * DD + c4];
            float4 r = {a.x + bb.x, a.y + bb.y, a.z + bb.z, a.w + bb.w};
            *(float4*)&g_emb[n * DD + c4] = r;
        }
    } else {
        if (tid < DD) {
            float s1 = 0.f, s2 = 0.f;
            #pragma unroll 8
            for (int c = 0; c < DD; c++) {
                float w = W[tid * DD + c];
                s1 = fmaf(w, a1[c], s1);
                s2 = fmaf(w, a2[c], s2);
            }
            g_wa1[tid] = s1; g_wa2[tid] = s2;
            float bsum = bp[tid];
            #pragma unroll 8
            for (int m = 0; m < DD; m++) bsum = fmaf(bo[m], Wp[(DD + m) * DD + tid], bsum);
            g_bc[tid] = bsum;
        }
        for (int o = tid; o < DD * DD; o += 256) {
            int k = o >> 6, c = o & 63;
            float acc = 0.f;
            #pragma unroll 8
            for (int m = 0; m < DD; m++)
                acc = fmaf(Wo[k * DD + m], Wp[(DD + m) * DD + c], acc);
            g_Wc[o] = acc;
        }
    }
}

// ============================================================
// Kernel B: fused projections (Wh, q, kt2, vt2) + Wh1/Wh2.
// grid (48, 23), block 256, 32 rows/block.
// ============================================================
#define BROWS 32
__global__ __launch_bounds__(256) void proj_kernel(
    const float* __restrict__ x,
    const float* __restrict__ W,  const float* __restrict__ Wq, const float* __restrict__ bq,
    const float* __restrict__ Wk, const float* __restrict__ bk,
    const float* __restrict__ Wv, const float* __restrict__ bv) {
    __shared__ float xs[BROWS][DD];
    __shared__ float ys[BROWS][DD];
    int s = blockIdx.x;
    int n0 = blockIdx.y * BROWS;
    int tid = threadIdx.x, lane = tid & 31, w = tid >> 5;

    #pragma unroll
    for (int half = 0; half < 2; half++) {
        int idx = half * 256 + tid;
        int r = idx >> 4, k4 = (idx & 15) * 4;
        int nn = min(n0 + r, NS - 1);
        float4 xv = *(const float4*)&x[(size_t)(s * NS + nn) * DD + k4];
        float4 ev = *(const float4*)&g_emb[nn * DD + k4];
        *(float4*)&xs[r][k4] = xv;
        float4 yv = {xv.x + ev.x, xv.y + ev.y, xv.z + ev.z, xv.w + ev.w};
        *(float4*)&ys[r][k4] = yv;
    }
    __syncthreads();

    // Wh1/Wh2
    {
        float wa10 = g_wa1[lane], wa11 = g_wa1[32 + lane];
        float wa20 = g_wa2[lane], wa21 = g_wa2[32 + lane];
        #pragma unroll
        for (int rr = 0; rr < 4; rr++) {
            int r = w * 4 + rr, n = n0 + r;
            float x0 = xs[r][lane], x1 = xs[r][32 + lane];
            float s1 = x0 * wa10 + x1 * wa11;
            float s2 = x0 * wa20 + x1 * wa21;
            #pragma unroll
            for (int off = 16; off; off >>= 1) {
                s1 += __shfl_xor_sync(0xffffffffu, s1, off);
                s2 += __shfl_xor_sync(0xffffffffu, s2, off);
            }
            if (lane == 0 && n < NS) {
                g_Wh1[s * NS + n] = s1;
                g_Wh2[s * NS + n] = s2;
            }
        }
    }

    int m = tid >> 6, c = tid & 63;
    const float* wp = (m == 0) ? W : (m == 1) ? Wq : (m == 2) ? Wk : Wv;
    float bias = 0.f;
    if (m == 1) bias = bq[c]; else if (m == 2) bias = bk[c]; else if (m == 3) bias = bv[c];

    float wcol[DD];
    #pragma unroll
    for (int k = 0; k < DD; k++) wcol[k] = wp[k * DD + c];

    int h = c >> 4, c2 = (c >> 1) & 7, phalf = c & 1;
    float* tp = ((m == 2) ? g_kt2 : g_vt2) +
                (size_t)(((s * 4 + h) * 8 + c2) * 720) * 2 + phalf;

    for (int r = 0; r < BROWS; r++) {
        int n = n0 + r;
        if (n >= NS) break;
        const float* src = (m == 0) ? xs[r] : ys[r];
        float acc = bias;
        #pragma unroll
        for (int k4 = 0; k4 < DD; k4 += 4) {
            float4 sv = *(const float4*)&src[k4];
            acc = fmaf(sv.x, wcol[k4],
                  fmaf(sv.y, wcol[k4 + 1],
                  fmaf(sv.z, wcol[k4 + 2],
                  fmaf(sv.w, wcol[k4 + 3], acc))));
        }
        if (m == 0)      g_Wh[(size_t)(s * NS + n) * DD + c] = acc;
        else if (m == 1) g_q[(size_t)(s * NS + n) * DD + c] = acc;
        else             tp[n * 2] = acc;
    }
}

// ============================================================
// Kernel D: GAT. grid (48,45), block 256.
// ============================================================
__global__ __launch_bounds__(256) void gat_kernel() {
    __shared__ float p[16][720];
    __shared__ float red[8][16];
    __shared__ float red1[8];
    __shared__ float smax;
    __shared__ float rowsum[16];

    int s = blockIdx.x, t = blockIdx.y;
    int i0 = t * 16;
    int tid = threadIdx.x, lane = tid & 31, w = tid >> 5;
    const unsigned* __restrict__ cm = g_cmask + t * NS;
    const float* __restrict__ wh2 = g_Wh2 + s * NS;

    float wh1[16];
    #pragma unroll
    for (int ti = 0; ti < 16; ti++) {
        int i = min(i0 + ti, NS - 1);
        wh1[ti] = g_Wh1[s * NS + i];
    }

    float lm = -FINF;
    for (int j = tid; j < NS; j += 256) lm = fmaxf(lm, wh2[j]);
    #pragma unroll
    for (int off = 16; off; off >>= 1)
        lm = fmaxf(lm, __shfl_xor_sync(0xffffffffu, lm, off));
    if (lane == 0) red1[w] = lm;
    __syncthreads();
    if (tid == 0) {
        float mm = red1[0];
        #pragma unroll
        for (int ww = 1; ww < 8; ww++) mm = fmaxf(mm, red1[ww]);
        smax = mm;
    }
    __syncthreads();

    float rme[16];
    {
        float mw = smax;
        #pragma unroll
        for (int ti = 0; ti < 16; ti++) {
            float e = wh1[ti] + mw;
            rme[ti] = fmaxf(e, 0.2f * e);
        }
    }

    float lsum[16];
    #pragma unroll
    for (int ti = 0; ti < 16; ti++) lsum[ti] = 0.f;
    for (int j = tid; j < NS; j += 256) {
        float w2 = wh2[j];
        unsigned mk = cm[j];
        #pragma unroll
        for (int ti = 0; ti < 16; ti++) {
            float e = wh1[ti] + w2;
            e = fmaxf(e, 0.2f * e);
            float pe = ((mk >> ti) & 1u) ? __expf(e - rme[ti]) : 0.0f;
            p[ti][j] = pe;
            lsum[ti] += pe;
        }
    }
    #pragma unroll
    for (int ti = 0; ti < 16; ti++)
        #pragma unroll
        for (int off = 16; off; off >>= 1)
            lsum[ti] += __shfl_xor_sync(0xffffffffu, lsum[ti], off);
    if (lane == 0) {
        #pragma unroll
        for (int ti = 0; ti < 16; ti++) red[w][ti] = lsum[ti];
    }
    __syncthreads();
    if (tid < 16) {
        float ss = red[0][tid];
        #pragma unroll
        for (int ww = 1; ww < 8; ww++) ss += red[ww][tid];
        rowsum[tid] = ss;
    }
    __syncthreads();

    int c = tid & 63, g = tid >> 6;
    float acc[16];
    #pragma unroll
    for (int ti = 0; ti < 16; ti++) acc[ti] = 0.f;
    const float* __restrict__ WhS = g_Wh + (size_t)s * NS * DD;
    for (int j0 = g * 4; j0 < NS; j0 += 16) {
        float wv0 = WhS[(size_t)(j0 + 0) * DD + c];
        float wv1 = WhS[(size_t)(j0 + 1) * DD + c];
        float wv2 = WhS[(size_t)(j0 + 2) * DD + c];
        float wv3 = WhS[(size_t)(j0 + 3) * DD + c];
        #pragma unroll
        for (int ti = 0; ti < 16; ti++) {
            float4 pv = *(const float4*)&p[ti][j0];
            acc[ti] = fmaf(pv.x, wv0, fmaf(pv.y, wv1,
                      fmaf(pv.z, wv2, fmaf(pv.w, wv3, acc[ti]))));
        }
    }
    __syncthreads();

    float* partial = &p[0][0];
    #pragma unroll
    for (int ti = 0; ti < 16; ti++) partial[(g * 16 + ti) * 64 + c] = acc[ti];
    __syncthreads();

    if (g == 0) {
        #pragma unroll
        for (int ti = 0; ti < 16; ti++) {
            int i = i0 + ti;
            if (i >= NS) continue;
            float v = (partial[ti * 64 + c] + partial[(16 + ti) * 64 + c] +
                       partial[(32 + ti) * 64 + c] + partial[(48 + ti) * 64 + c]) / rowsum[ti];
            v = v > 0.f ? v : expm1f(v);
            g_cat[(size_t)(s * NS + i) * 2 * DD + c] = v;
        }
    }
}

// ============================================================
// Kernel E: MHA — double-buffered cp.async k/v tiles, 4 q/warp, f32x2.
// grid (48, 45, 4), block 128 (4 warps).
// ============================================================
__global__ __launch_bounds__(128, 3) void mha_kernel() {
    __shared__ __align__(16) unsigned long long sbuf[4096];  // 2 x (k 1024 | v 1024); red overlay

    int s = blockIdx.x;
    int i0 = blockIdx.y * 16;
    int h = blockIdx.z;
    int tid = threadIdx.x, lane = tid & 31, w = tid >> 5;

    // q in registers, pre-scaled by 1/sqrt(16)
    unsigned long long qreg[4][8];
    #pragma unroll
    for (int tq = 0; tq < 4; tq++) {
        int iq = min(i0 + w * 4 + tq, NS - 1);
        const float2* qp2 = (const float2*)(g_q + (size_t)(s * NS + iq) * DD + h * 16);
        #pragma unroll
        for (int c2 = 0; c2 < 8; c2++) {
            float2 v = qp2[c2];
            qreg[tq][c2] = pack2(v.x * 0.25f, v.y * 0.25f);
        }
    }

    const float* __restrict__ ktf = g_kt2 + (size_t)(s * 4 + h) * 8 * 720 * 2;
    const float* __restrict__ vtf = g_vt2 + (size_t)(s * 4 + h) * 8 * 720 * 2;
    unsigned sbase = (unsigned)__cvta_generic_to_shared(sbuf);

    unsigned long long acc2[4][8];
    #pragma unroll
    for (int tq = 0; tq < 4; tq++)
        #pragma unroll
        for (int c2 = 0; c2 < 8; c2++) acc2[tq][c2] = 0ull;
    float l[4] = {0.f, 0.f, 0.f, 0.f};

    // prologue: async fill tile 0 into buf 0
    {
        #pragma unroll
        for (int i = 0; i < 4; i++) {
            int f = i * 128 + tid;
            int c2 = f >> 6, jp = f & 63;
            int j = jp * 2;
            if (j < NS) {
                unsigned dst = sbase + (unsigned)(c2 * 128 + jp * 2) * 8;
                cp_async16(dst, ktf + (c2 * 720 + j) * 2);
                cp_async16(dst + 1024 * 8, vtf + (c2 * 720 + j) * 2);
            }
        }
        asm volatile("cp.async.commit_group;");
    }

    for (int t = 0; t < 6; t++) {
        asm volatile("cp.async.wait_group 0;");
        __syncthreads();     // tile t visible to all; all warps done with buf[(t+1)&1]
        if (t < 5) {
            int jb = (t + 1) * 128;
            unsigned bufo = ((unsigned)((t + 1) & 1)) * 2048 * 8;
            #pragma unroll
            for (int i = 0; i < 4; i++) {
                int f = i * 128 + tid;
                int c2 = f >> 6, jp = f & 63;
                int j = jb + jp * 2;
                if (j < NS) {    // stale lanes are finite + exp-masked; no zero-fill needed
                    unsigned dst = sbase + bufo + (unsigned)(c2 * 128 + jp * 2) * 8;
                    cp_async16(dst, ktf + (c2 * 720 + j) * 2);
                    cp_async16(dst + 1024 * 8, vtf + (c2 * 720 + j) * 2);
                }
            }
            asm volatile("cp.async.commit_group;");
        }

        const unsigned long long* ks = sbuf + (t & 1) * 2048;
        const unsigned long long* vs = ks + 1024;
        int jb = t * 128;
        #pragma unroll
        for (int sub = 0; sub < 4; sub++) {
            int jl = sub * 32 + lane;
            bool ok = (jb + jl) < NS;
            unsigned long long sco2[4] = {0ull, 0ull, 0ull, 0ull};
            #pragma unroll
            for (int c2 = 0; c2 < 8; c2++) {
                unsigned long long kv = ks[c2 * 128 + jl];
                sco2[0] = ffma2(qreg[0][c2], kv, sco2[0]);
                sco2[1] = ffma2(qreg[1][c2], kv, sco2[1]);
                sco2[2] = ffma2(qreg[2][c2], kv, sco2[2]);
                sco2[3] = ffma2(qreg[3][c2], kv, sco2[3]);
            }
            unsigned long long p2[4];
            #pragma unroll
            for (int tq = 0; tq < 4; tq++) {
                float lo, hi;
                unpack2(sco2[tq], lo, hi);
                float pe = ok ? __expf(lo + hi) : 0.0f;
                l[tq] += pe;
                p2[tq] = pack2(pe, pe);
            }
            #pragma unroll
            for (int c2 = 0; c2 < 8; c2++) {
                unsigned long long vv = vs[c2 * 128 + jl];
                acc2[0][c2] = ffma2(p2[0], vv, acc2[0][c2]);
                acc2[1][c2] = ffma2(p2[1], vv, acc2[1][c2]);
                acc2[2][c2] = ffma2(p2[2], vv, acc2[2][c2]);
                acc2[3][c2] = ffma2(p2[3], vv, acc2[3][c2]);
            }
        }
    }

    // reduce l across lanes
    #pragma unroll
    for (int tq = 0; tq < 4; tq++)
        #pragma unroll
        for (int off = 16; off; off >>= 1)
            l[tq] += __shfl_xor_sync(0xffffffffu, l[tq], off);
    float linv[4];
    #pragma unroll
    for (int tq = 0; tq < 4; tq++) linv[tq] = 1.0f / l[tq];

    __syncthreads();   // all smem tile reads done before overlay
    unsigned long long* red = sbuf + w * 528;   // [16][33] per warp
    #pragma unroll
    for (int ps = 0; ps < 2; ps++) {
        #pragma unroll
        for (int tq2 = 0; tq2 < 2; tq2++)
            #pragma unroll
            for (int c2 = 0; c2 < 8; c2++)
                red[(tq2 * 8 + c2) * 33 + lane] = acc2[ps * 2 + tq2][c2];
        __syncwarp();
        int tql = lane >> 4, cl = lane & 15;
        const float* base = (const float*)&red[(tql * 8 + (cl >> 1)) * 33];
        int hf = cl & 1;
        float v = 0.f;
        #pragma unroll
        for (int ll = 0; ll < 32; ll++) v += base[ll * 2 + hf];
        float li = linv[ps * 2 + tql];
        int i = i0 + w * 4 + ps * 2 + tql;
        if (i < NS)
            g_cat[(size_t)(s * NS + i) * 2 * DD + DD + h * 16 + cl] = v * li;
        __syncwarp();
    }
}

// ============================================================
// Kernel F: final projection, 16 rows/block, 4-way k-split.
// ============================================================
__global__ __launch_bounds__(256) void final_kernel(const float* __restrict__ Wp,
                                                    float* __restrict__ out) {
    __shared__ float cs[16][2 * DD];
    __shared__ float pa[4][16][64];
    int s = blockIdx.x;
    int n0 = blockIdx.y * 16;
    int tid = threadIdx.x;

    #pragma unroll
    for (int half = 0; half < 2; half++) {
        int idx = half * 256 + tid;
        int r = idx >> 5, k4 = (idx & 31) * 4;
        int nn = min(n0 + r, NS - 1);
        *(float4*)&cs[r][k4] = *(const float4*)&g_cat[(size_t)(s * NS + nn) * 2 * DD + k4];
    }
    __syncthreads();

    int c = tid & 63, kg = tid >> 6;
    float acc[16];
    #pragma unroll
    for (int r = 0; r < 16; r++) acc[r] = 0.f;
    for (int k0 = kg * 32; k0 < kg * 32 + 32; k0 += 4) {
        const float* wsrc = (k0 < 64) ? (Wp + k0 * DD) : (g_Wc + (k0 - 64) * DD);
        float wv0 = wsrc[c];
        float wv1 = wsrc[DD + c];
        float wv2 = wsrc[2 * DD + c];
        float wv3 = wsrc[3 * DD + c];
        #pragma unroll
        for (int r = 0; r < 16; r++) {
            float4 cv = *(const float4*)&cs[r][k0];
            acc[r] = fmaf(cv.x, wv0, fmaf(cv.y, wv1,
                     fmaf(cv.z, wv2, fmaf(cv.w, wv3, acc[r]))));
        }
    }
    #pragma unroll
    for (int r = 0; r < 16; r++) pa[kg][r][c] = acc[r];
    __syncthreads();

    if (kg == 0) {
        #pragma unroll
        for (int r = 0; r < 16; r++) {
            int n = n0 + r;
            if (n < NS)
                out[(size_t)(s * NS + n) * DD + c] =
                    pa[0][r][c] + pa[1][r][c] + pa[2][r][c] + pa[3][r][c] + g_bc[c];
        }
    }
}

// ============================================================
extern "C" void kernel_launch(void* const* d_in, const int* in_sizes, int n_in,
                              void* d_out, int out_size) {
    const float* x      = (const float*)d_in[0];
    const int*   adj    = (const int*)d_in[1];
    const int*   ind    = (const int*)d_in[2];
    const int*   outd   = (const int*)d_in[3];
    const float* in_emb = (const float*)d_in[4];
    const float* out_emb= (const float*)d_in[5];
    const float* W      = (const float*)d_in[6];
    const float* a1     = (const float*)d_in[7];
    const float* a2     = (const float*)d_in[8];
    const float* Wq     = (const float*)d_in[9];
    const float* bq     = (const float*)d_in[10];
    const float* Wk     = (const float*)d_in[11];
    const float* bk     = (const float*)d_in[12];
    const float* Wv     = (const float*)d_in[13];
    const float* bv     = (const float*)d_in[14];
    const float* Wo     = (const float*)d_in[15];
    const float* bo     = (const float*)d_in[16];
    const float* Wp     = (const float*)d_in[17];
    const float* bp     = (const float*)d_in[18];
    float* out = (float*)d_out;

    pre_kernel<<<181, 256>>>(adj, in_emb, out_emb, ind, outd, W, a1, a2, Wo, bo, Wp, bp);
    proj_kernel<<<dim3(NSAMP, (NS + BROWS - 1) / BROWS), 256>>>(x, W, Wq, bq, Wk, bk, Wv, bv);
    gat_kernel<<<dim3(NSAMP, NTILE), 256>>>();
    mha_kernel<<<dim3(NSAMP, NTILE, 4), 128>>>();
    final_kernel<<<dim3(NSAMP, NTILE), 256>>>(Wp, out);
}